// round 5
// baseline (speedup 1.0000x reference)
#include <cuda_runtime.h>

#define BB 8
#define CC 4
#define HH 512
#define WW 512
#define RPW 8                          // rows per warp strip
#define NSTRIPS (HH / RPW)             // 64
#define NPLANE (BB * CC)               // 32
#define CGRP 4                         // column groups of 128
#define NT 128
#define WPB (NT / 32)                  // 4 warps/block
#define NBLK (NPLANE * NSTRIPS * CGRP / WPB)   // 2048

// One float4 partial per block (pt, p, t, mismatch). Block b covers a single
// plane (b >> 6), since each plane spans 64 consecutive blocks.
__device__ float4 g_part[NBLK];
__device__ int g_ctr = 0;

__device__ __forceinline__ float sigm(float x) {
    float t;
    asm("tanh.approx.f32 %0, %1;" : "=f"(t) : "f"(0.5f * x));
    return __fmaf_rn(0.5f, t, 0.5f);
}
__device__ __forceinline__ unsigned prmt(unsigned a, unsigned b, unsigned s) {
    unsigned r;
    asm("prmt.b32 %0, %1, %2, %3;" : "=r"(r) : "r"(a), "r"(b), "r"(s));
    return r;
}

struct Row {
    float s0, s1, s2, s3, d0, d1, d2, d3;   // horizontal sobel partials (probs)
    unsigned sb, db;                        // packed-byte partials (targets)
};

// Fetch one image row (or zero halo), build horizontal partials, optionally
// accumulate dice sums. Horizontal neighbors via warp shuffle; warp-edge
// lanes (0 / 31) do predicated scalar loads.
template <bool DICE>
__device__ __forceinline__ Row fetch(const float* __restrict__ lg,
                                     const float* __restrict__ tg,
                                     int gr, int c0, int lane,
                                     bool lEdge, bool rEdge,
                                     float& s_pt, float& s_p, int& s_ti)
{
    float4 pv = make_float4(0.f, 0.f, 0.f, 0.f);
    unsigned tw = 0;
    const bool in = ((unsigned)gr < (unsigned)HH);
    const float* rowp = lg + (size_t)gr * WW + c0;
    const float* rowt = tg + (size_t)gr * WW + c0;
    if (in) {
        float4 x  = __ldg((const float4*)rowp);
        float4 tv = __ldg((const float4*)rowt);
        pv.x = sigm(x.x); pv.y = sigm(x.y); pv.z = sigm(x.z); pv.w = sigm(x.w);
        // pack targets (t in {0.0f,1.0f}): byte3 of bits is 0x3F/0x00, byte0 always 0
        unsigned p1 = prmt(__float_as_uint(tv.x), __float_as_uint(tv.y), 0x0073u);
        unsigned p2 = prmt(__float_as_uint(tv.z), __float_as_uint(tv.w), 0x7300u);
        tw = (p1 | p2) & 0x01010101u;
        if (DICE) {
            s_pt = __fmaf_rn(pv.x, tv.x, s_pt);
            s_pt = __fmaf_rn(pv.y, tv.y, s_pt);
            s_pt = __fmaf_rn(pv.z, tv.z, s_pt);
            s_pt = __fmaf_rn(pv.w, tv.w, s_pt);
            s_p += (pv.x + pv.y) + (pv.z + pv.w);
            s_ti += __popc(tw);               // bytes are 0/1
        }
    }
    // warp-edge neighbor values
    float eL = 0.f, eR = 0.f;
    unsigned tL = 0, tR = 0;
    if (lane == 0 && lEdge && in) {
        eL = sigm(__ldg(rowp - 1));
        tL = __float_as_uint(__ldg(rowt - 1)) >> 29;
    }
    if (lane == 31 && rEdge && in) {
        eR = sigm(__ldg(rowp + 4));
        tR = __float_as_uint(__ldg(rowt + 4)) >> 29;
    }
    float    plin = __shfl_up_sync(0xffffffffu, pv.w, 1);
    float    prin = __shfl_down_sync(0xffffffffu, pv.x, 1);
    unsigned twl  = __shfl_up_sync(0xffffffffu, tw, 1);
    unsigned twr  = __shfl_down_sync(0xffffffffu, tw, 1);
    float pl = (lane == 0)  ? eL : plin;
    float pr = (lane == 31) ? eR : prin;
    unsigned tl = (lane == 0)  ? tL : (twl >> 24);
    unsigned tr = (lane == 31) ? tR : (twr & 0xffu);

    Row h;
    h.s0 = __fmaf_rn(2.f, pv.x, pl   + pv.y); h.d0 = pv.y - pl;
    h.s1 = __fmaf_rn(2.f, pv.y, pv.x + pv.z); h.d1 = pv.z - pv.x;
    h.s2 = __fmaf_rn(2.f, pv.z, pv.y + pv.w); h.d2 = pv.w - pv.y;
    h.s3 = __fmaf_rn(2.f, pv.w, pv.z + pr);   h.d3 = pr   - pv.z;
    unsigned wl = (tw << 8) | tl;
    unsigned wr = (tw >> 8) | (tr << 24);
    h.sb = wl + 2u * tw + wr;                 // lanes in [0,4]
    h.db = (wr + 0x02020202u) - wl;           // lanes in [1,3] (bias +2)
    return h;
}

__device__ __forceinline__ int combine(const Row& h0, const Row& h1, const Row& h2)
{
    float gx0 = __fmaf_rn(2.f, h1.d0, h0.d0 + h2.d0);
    float gx1 = __fmaf_rn(2.f, h1.d1, h0.d1 + h2.d1);
    float gx2 = __fmaf_rn(2.f, h1.d2, h0.d2 + h2.d2);
    float gx3 = __fmaf_rn(2.f, h1.d3, h0.d3 + h2.d3);
    float gy0 = h2.s0 - h0.s0;
    float gy1 = h2.s1 - h0.s1;
    float gy2 = h2.s2 - h0.s2;
    float gy3 = h2.s3 - h0.s3;
    bool pb0 = __fmaf_rn(gx0, gx0, gy0 * gy0) > 0.25f;
    bool pb1 = __fmaf_rn(gx1, gx1, gy1 * gy1) > 0.25f;
    bool pb2 = __fmaf_rn(gx2, gx2, gy2 * gy2) > 0.25f;
    bool pb3 = __fmaf_rn(gx3, gx3, gy3 * gy3) > 0.25f;

    unsigned hx = h0.db + 2u * h1.db + h2.db;     // ==8 per lane <=> hx_true==0
    unsigned hy = (h2.sb + 0x04040404u) - h0.sb;  // ==4 per lane <=> hy_true==0
    unsigned cmb = (hx ^ 0x08080808u) | (hy ^ 0x04040404u);

    int m = 0;
    m += (int)(pb0 != ((cmb & 0x000000FFu) != 0));
    m += (int)(pb1 != ((cmb & 0x0000FF00u) != 0));
    m += (int)(pb2 != ((cmb & 0x00FF0000u) != 0));
    m += (int)(pb3 != ((cmb >> 24) != 0));
    return m;
}

__global__ __launch_bounds__(NT) void loss_fused(
    const float* __restrict__ logits, const float* __restrict__ targets,
    const float* __restrict__ cw, float* __restrict__ out)
{
    __shared__ float red[WPB][4];
    __shared__ float s_dice[NPLANE];
    __shared__ float s_mm[NPLANE];
    __shared__ int s_isLast;

    const int lane = threadIdx.x & 31;
    const int gw = blockIdx.x * WPB + (threadIdx.x >> 5);
    const int cg    = gw & 3;                    // column group 0..3
    const int strip = (gw >> 2) & (NSTRIPS - 1); // 0..63
    const int plane = gw >> 8;                   // 0..31
    const int c0 = cg * 128 + lane * 4;
    const bool lEdge = (cg > 0);
    const bool rEdge = (cg < 3);
    const int row0 = strip * RPW;

    const float* lg = logits  + (size_t)plane * HH * WW;
    const float* tg = targets + (size_t)plane * HH * WW;

    float s_pt = 0.f, s_p = 0.f;
    int s_ti = 0, s_mi = 0;

    Row h0 = fetch<false>(lg, tg, row0 - 1, c0, lane, lEdge, rEdge, s_pt, s_p, s_ti);
    Row h1 = fetch<true >(lg, tg, row0,     c0, lane, lEdge, rEdge, s_pt, s_p, s_ti);
    #pragma unroll
    for (int k = 0; k < RPW - 1; k++) {
        Row h2 = fetch<true>(lg, tg, row0 + k + 1, c0, lane, lEdge, rEdge, s_pt, s_p, s_ti);
        s_mi += combine(h0, h1, h2);
        h0 = h1; h1 = h2;
    }
    {   // last window: bottom halo row (no dice)
        Row h2 = fetch<false>(lg, tg, row0 + RPW, c0, lane, lEdge, rEdge, s_pt, s_p, s_ti);
        s_mi += combine(h0, h1, h2);
    }

    // ---- warp reduce ----
    float s_t = (float)s_ti, s_m = (float)s_mi;
    #pragma unroll
    for (int o = 16; o > 0; o >>= 1) {
        s_pt += __shfl_down_sync(0xffffffffu, s_pt, o);
        s_p  += __shfl_down_sync(0xffffffffu, s_p,  o);
        s_t  += __shfl_down_sync(0xffffffffu, s_t,  o);
        s_m  += __shfl_down_sync(0xffffffffu, s_m,  o);
    }
    int w = threadIdx.x >> 5;
    if (lane == 0) {
        red[w][0] = s_pt; red[w][1] = s_p; red[w][2] = s_t; red[w][3] = s_m;
    }
    __syncthreads();
    if (threadIdx.x == 0) {
        float a = 0.f, b = 0.f, c2 = 0.f, d = 0.f;
        #pragma unroll
        for (int j = 0; j < WPB; j++) {
            a += red[j][0]; b += red[j][1]; c2 += red[j][2]; d += red[j][3];
        }
        g_part[blockIdx.x] = make_float4(a, b, c2, d);
        __threadfence();
        int v = atomicAdd(&g_ctr, 1);
        s_isLast = (v == NBLK - 1);
    }
    __syncthreads();

    // ---- final reduction in last block ----
    if (s_isLast) {
        __threadfence();
        int tid = threadIdx.x;
        if (tid < NPLANE) {
            float a = 0.f, b = 0.f, c2 = 0.f, m = 0.f;
            #pragma unroll 8
            for (int s = 0; s < NBLK / NPLANE; s++) {
                float4 v = g_part[tid * (NBLK / NPLANE) + s];
                a += v.x; b += v.y; c2 += v.z; m += v.w;
            }
            s_dice[tid] = (2.0f * a + 1.0f) / (b + c2 + 1.0f);  // SMOOTH=1
            s_mm[tid] = m;
        }
        __syncthreads();
        if (tid == 0) {
            float mt = 0.0f;
            #pragma unroll
            for (int j = 0; j < NPLANE; j++) mt += s_mm[j];

            float wsum = 0.0f, dl = 0.0f;
            #pragma unroll
            for (int c = 0; c < CC; c++) {
                float acc = 0.0f;
                #pragma unroll
                for (int b = 0; b < BB; b++) acc += s_dice[b * CC + c];
                dl += cw[c] * (1.0f - acc / (float)BB);
                wsum += cw[c];
            }
            dl /= wsum;
            float bl = 100.0f * mt / (float)((long long)BB * CC * HH * WW);
            out[0] = 0.7f * dl + 0.3f * bl;
            g_ctr = 0;   // reset for next graph replay
        }
    }
}

extern "C" void kernel_launch(void* const* d_in, const int* in_sizes, int n_in,
                              void* d_out, int out_size)
{
    const float* logits  = (const float*)d_in[0];
    const float* targets = (const float*)d_in[1];
    const float* cw      = (const float*)d_in[2];

    loss_fused<<<NBLK, NT>>>(logits, targets, cw, (float*)d_out);
}